// round 4
// baseline (speedup 1.0000x reference)
#include <cuda_runtime.h>

#define BB 64
#define CC 512
#define TT 16
#define HWD 196
#define KK 8
#define CPB 4            // channels per pool block

// [b][t][c] per-channel partial scores
__device__ float g_partial[BB * TT * CC];
// [b][t] -> output slot 0..15 (0-7 = approx pos, 8-15 = 8+detail pos)
__device__ int   g_dest[BB * TT];

// ---------------------------------------------------------------------------
// Kernel 1: one block per 4 consecutive (b,c) slabs, 256 threads.
//   phase 1: pooled[ch][t][blk] from global via 2x LDG.64 (12-13 iters/thread
//            -> deep MLP), stored once to smem (3136 floats)
//   phase 2: sc[ch][blk] = sum_t pooled[ch][t][blk]   (196 threads)
//   phase 3: thread (ch=tid>>6, t=(tid>>2)&15, g=tid&3) accumulates
//            pooled[ch][t][blk]*sc[ch][blk] over blk in {g, g+4, ...},
//            4-lane shuffle reduce -> partial[b][t][c]
// ---------------------------------------------------------------------------
__global__ __launch_bounds__(256) void k_pool(const float* __restrict__ x) {
    __shared__ float pooled[CPB * TT * 49];   // 3136
    __shared__ float sc[CPB * 49];            // 196

    const int bc0 = blockIdx.x * CPB;         // first b*CC + c of this block
    const float* __restrict__ base = x + (size_t)bc0 * (TT * HWD);

    #pragma unroll 13
    for (int p = threadIdx.x; p < CPB * TT * 49; p += 256) {
        int tch = p / 49;                     // ch*16 + t
        int blk = p - tch * 49;
        int by = blk / 7, bx = blk - by * 7;
        const float* r = base + tch * HWD + by * 28 + bx * 2;
        float2 a = *(const float2*)r;
        float2 b = *(const float2*)(r + 14);
        pooled[p] = 0.25f * (a.x + a.y + b.x + b.y);
    }
    __syncthreads();

    if (threadIdx.x < CPB * 49) {
        int ch = threadIdx.x / 49, blk = threadIdx.x - ch * 49;
        const float* pc = pooled + ch * (TT * 49) + blk;
        float s = 0.f;
        #pragma unroll
        for (int t = 0; t < TT; t++) s += pc[t * 49];
        sc[threadIdx.x] = s;
    }
    __syncthreads();

    const int ch = threadIdx.x >> 6;
    const int t  = (threadIdx.x >> 2) & 15;
    const int g  = threadIdx.x & 3;
    const float* pr = pooled + ch * (TT * 49) + t * 49;
    const float* sr = sc + ch * 49;
    float acc = 0.f;
    #pragma unroll
    for (int blk = g; blk < 49; blk += 4)
        acc += pr[blk] * sr[blk];
    acc += __shfl_xor_sync(0xffffffffu, acc, 2);
    acc += __shfl_xor_sync(0xffffffffu, acc, 1);
    if (g == 0) {
        int bc = bc0 + ch;
        int b = bc >> 9, c = bc & (CC - 1);
        g_partial[(b * TT + t) * CC + c] = acc;
    }
}

// ---------------------------------------------------------------------------
// Kernel 2: fused channel-reduce + selection. One block per b, 256 threads.
// Deterministic fixed-order sums; jax.lax.top_k tie semantics (ties by
// smaller index) for both largest (approx) and smallest (detail) halves.
// ---------------------------------------------------------------------------
__global__ __launch_bounds__(256) void k_score_select() {
    __shared__ float v[TT];
    __shared__ int fa[TT], fd[TT];
    const int b = blockIdx.x;
    const int t = threadIdx.x >> 4;
    const int g = threadIdx.x & 15;

    const float* __restrict__ p = g_partial + (b * TT + t) * CC;
    float s = 0.f;
    #pragma unroll
    for (int j = 0; j < CC / 16; j++) s += p[g + 16 * j];
    s += __shfl_xor_sync(0xffffffffu, s, 8);
    s += __shfl_xor_sync(0xffffffffu, s, 4);
    s += __shfl_xor_sync(0xffffffffu, s, 2);
    s += __shfl_xor_sync(0xffffffffu, s, 1);
    if (g == 0)
        v[t] = s * (1.0f / (float)(CC * TT)) + ((t & 1) == 0 ? 1.0f : 0.0f);
    __syncthreads();

    if (threadIdx.x < TT) {
        const int i = threadIdx.x;
        const float mv = v[i];
        int ra = 0, rd = 0;
        #pragma unroll
        for (int j = 0; j < TT; j++) {
            ra += (v[j] > mv) || (v[j] == mv && j < i);
            rd += (v[j] < mv) || (v[j] == mv && j < i);
        }
        fa[i] = (ra < KK);
        fd[i] = (rd < KK);
    }
    __syncthreads();
    if (threadIdx.x < TT) {
        const int i = threadIdx.x;
        int pa = 0, pd = 0;
        for (int j = 0; j < i; j++) { pa += fa[j]; pd += fd[j]; }
        // ranks form a permutation (ra+rd==15): exactly one of fa/fd is set
        g_dest[b * TT + i] = fa[i] ? pa : (KK + pd);
    }
}

// ---------------------------------------------------------------------------
// Kernel 3: gather. Sequential coalesced READ of the whole input; permuted
// frame-granular WRITE into [x_a ; x_d].
// ---------------------------------------------------------------------------
#define TOTAL4 (BB * CC * TT * (HWD / 4))   // 25,690,112 float4s

__global__ __launch_bounds__(256) void k_gather(const float* __restrict__ x,
                                                float* __restrict__ out) {
    unsigned i = blockIdx.x * 256 + threadIdx.x;
    if (i >= TOTAL4) return;
    float4 val = __ldg(&((const float4*)x)[i]);
    unsigned hw4 = i % 49u;
    unsigned r = i / 49u;
    unsigned t = r & (TT - 1);
    unsigned c = (r >> 4) & (CC - 1);
    unsigned b = r >> 13;
    int s = __ldg(&g_dest[b * TT + t]);
    unsigned half = (unsigned)s >> 3;
    unsigned j = (unsigned)s & (KK - 1);
    unsigned o = half * (BB * CC * KK * 49u) + ((b * CC + c) * KK + j) * 49u + hw4;
    ((float4*)out)[o] = val;
}

// ---------------------------------------------------------------------------
extern "C" void kernel_launch(void* const* d_in, const int* in_sizes, int n_in,
                              void* d_out, int out_size) {
    const float* x = (const float*)d_in[0];
    float* out = (float*)d_out;

    k_pool<<<(BB * CC) / CPB, 256>>>(x);
    k_score_select<<<BB, 256>>>();
    k_gather<<<(TOTAL4 + 255) / 256, 256>>>(x, out);
}

// round 5
// speedup vs baseline: 1.1232x; 1.1232x over previous
#include <cuda_runtime.h>

#define BB 64
#define CC 512
#define TT 16
#define HWD 196
#define KK 8
#define CPB 2            // channels per pool block

// [b][t][c] per-channel partial scores
__device__ float g_partial[BB * TT * CC];
// [b][t] -> output slot 0..15 (0-7 = approx pos, 8-15 = 8+detail pos)
__device__ int   g_dest[BB * TT];

// ---------------------------------------------------------------------------
// Kernel 1: one block per 2 consecutive (b,c) slabs, 256 threads.
//   phase 1: thread p<224 owns strip (ch,t,y): rows 2y,2y+1 of frame t =
//            28 contiguous aligned floats = 7 INDEPENDENT float4 LDGs.
//            Computes 7 pooled values with static register lane picks, 7 STS.
//   phase 2: sc[ch][blk] = sum_t pooled[ch][t][blk]   (98 threads)
//   phase 3: thread (ch=tid>>7, t=(tid>>3)&15, g=tid&7) accumulates
//            pooled[ch][t][blk]*sc[ch][blk] over blk in {g, g+8, ...},
//            8-lane shuffle reduce -> partial[b][t][c]
// ---------------------------------------------------------------------------
__global__ __launch_bounds__(256) void k_pool(const float* __restrict__ x) {
    __shared__ float pooled[CPB * TT * 49];   // 1568
    __shared__ float sc[CPB * 49];            // 98

    const int bc0 = blockIdx.x * CPB;
    const float* __restrict__ base = x + (size_t)bc0 * (TT * HWD);

    const int p = threadIdx.x;
    if (p < CPB * TT * 7) {                   // 224 strips
        int ch = p / 112;
        int q  = p - ch * 112;
        int t  = q / 7;
        int y  = q - t * 7;                   // pool row 0..6 (input rows 2y,2y+1)
        const float4* __restrict__ src =
            (const float4*)(base + ch * (TT * HWD) + t * HWD + y * 28);
        float4 r0 = src[0], r1 = src[1], r2 = src[2], r3 = src[3];
        float4 r4 = src[4], r5 = src[5], r6 = src[6];
        float* dst = pooled + ch * (TT * 49) + t * 49 + y * 7;
        dst[0] = 0.25f * (r0.x + r0.y + r3.z + r3.w);
        dst[1] = 0.25f * (r0.z + r0.w + r4.x + r4.y);
        dst[2] = 0.25f * (r1.x + r1.y + r4.z + r4.w);
        dst[3] = 0.25f * (r1.z + r1.w + r5.x + r5.y);
        dst[4] = 0.25f * (r2.x + r2.y + r5.z + r5.w);
        dst[5] = 0.25f * (r2.z + r2.w + r6.x + r6.y);
        dst[6] = 0.25f * (r3.x + r3.y + r6.z + r6.w);
    }
    __syncthreads();

    if (threadIdx.x < CPB * 49) {
        int ch = threadIdx.x / 49, blk = threadIdx.x - ch * 49;
        const float* pc = pooled + ch * (TT * 49) + blk;
        float s = 0.f;
        #pragma unroll
        for (int t = 0; t < TT; t++) s += pc[t * 49];
        sc[threadIdx.x] = s;
    }
    __syncthreads();

    const int ch = threadIdx.x >> 7;
    const int t  = (threadIdx.x >> 3) & 15;
    const int g  = threadIdx.x & 7;
    const float* pr = pooled + ch * (TT * 49) + t * 49;
    const float* sr = sc + ch * 49;
    float acc = 0.f;
    #pragma unroll
    for (int blk = g; blk < 49; blk += 8)
        acc += pr[blk] * sr[blk];
    acc += __shfl_xor_sync(0xffffffffu, acc, 4);
    acc += __shfl_xor_sync(0xffffffffu, acc, 2);
    acc += __shfl_xor_sync(0xffffffffu, acc, 1);
    if (g == 0) {
        int bc = bc0 + ch;
        int b = bc >> 9, c = bc & (CC - 1);
        g_partial[(b * TT + t) * CC + c] = acc;
    }
}

// ---------------------------------------------------------------------------
// Kernel 2: fused channel-reduce + selection. One block per b, 256 threads.
// Deterministic fixed-order sums; jax.lax.top_k tie semantics (ties by
// smaller index) for both largest (approx) and smallest (detail) halves.
// ---------------------------------------------------------------------------
__global__ __launch_bounds__(256) void k_score_select() {
    __shared__ float v[TT];
    __shared__ int fa[TT], fd[TT];
    const int b = blockIdx.x;
    const int t = threadIdx.x >> 4;
    const int g = threadIdx.x & 15;

    const float* __restrict__ p = g_partial + (b * TT + t) * CC;
    float s = 0.f;
    #pragma unroll
    for (int j = 0; j < CC / 16; j++) s += p[g + 16 * j];
    s += __shfl_xor_sync(0xffffffffu, s, 8);
    s += __shfl_xor_sync(0xffffffffu, s, 4);
    s += __shfl_xor_sync(0xffffffffu, s, 2);
    s += __shfl_xor_sync(0xffffffffu, s, 1);
    if (g == 0)
        v[t] = s * (1.0f / (float)(CC * TT)) + ((t & 1) == 0 ? 1.0f : 0.0f);
    __syncthreads();

    if (threadIdx.x < TT) {
        const int i = threadIdx.x;
        const float mv = v[i];
        int ra = 0, rd = 0;
        #pragma unroll
        for (int j = 0; j < TT; j++) {
            ra += (v[j] > mv) || (v[j] == mv && j < i);
            rd += (v[j] < mv) || (v[j] == mv && j < i);
        }
        fa[i] = (ra < KK);
        fd[i] = (rd < KK);
    }
    __syncthreads();
    if (threadIdx.x < TT) {
        const int i = threadIdx.x;
        int pa = 0, pd = 0;
        for (int j = 0; j < i; j++) { pa += fa[j]; pd += fd[j]; }
        // ranks form a permutation (ra+rd==15): exactly one of fa/fd is set
        g_dest[b * TT + i] = fa[i] ? pa : (KK + pd);
    }
}

// ---------------------------------------------------------------------------
// Kernel 3: gather. Sequential coalesced READ of the whole input; permuted
// frame-granular WRITE into [x_a ; x_d].
// ---------------------------------------------------------------------------
#define TOTAL4 (BB * CC * TT * (HWD / 4))   // 25,690,112 float4s

__global__ __launch_bounds__(256) void k_gather(const float* __restrict__ x,
                                                float* __restrict__ out) {
    unsigned i = blockIdx.x * 256 + threadIdx.x;
    if (i >= TOTAL4) return;
    float4 val = __ldg(&((const float4*)x)[i]);
    unsigned hw4 = i % 49u;
    unsigned r = i / 49u;
    unsigned t = r & (TT - 1);
    unsigned c = (r >> 4) & (CC - 1);
    unsigned b = r >> 13;
    int s = __ldg(&g_dest[b * TT + t]);
    unsigned half = (unsigned)s >> 3;
    unsigned j = (unsigned)s & (KK - 1);
    unsigned o = half * (BB * CC * KK * 49u) + ((b * CC + c) * KK + j) * 49u + hw4;
    ((float4*)out)[o] = val;
}

// ---------------------------------------------------------------------------
extern "C" void kernel_launch(void* const* d_in, const int* in_sizes, int n_in,
                              void* d_out, int out_size) {
    const float* x = (const float*)d_in[0];
    float* out = (float*)d_out;

    k_pool<<<(BB * CC) / CPB, 256>>>(x);
    k_score_select<<<BB, 256>>>();
    k_gather<<<(TOTAL4 + 255) / 256, 256>>>(x, out);
}